// round 16
// baseline (speedup 1.0000x reference)
#include <cuda_runtime.h>
#include <cuda_bf16.h>
#include <cstdint>

// Problem constants
constexpr int GM = 32768;          // B*S rows
constexpr int GK = 1024;           // F
constexpr int GN = 1024;           // F
constexpr int ATT_SIZE = 33554432; // B*S*F
constexpr int NBH = 64;            // B*H
constexpr int NSLAB = 8192;        // rows per head slab
constexpr int NCHUNK = 32;         // row chunks per slab for P accumulation

// -------------------- scratch (device globals; no allocs allowed) ----------
__device__ float g_Qp[(size_t)GM * GN];
__device__ float g_Kp[(size_t)GM * GN];
__device__ float g_Vp[(size_t)GM * GN];
__device__ float g_Ppart[(size_t)NBH * NCHUNK * 4096];
__device__ float g_wt[3][(size_t)GK * GN];   // W^T, tf32-rounded, [N][K]

// -------------------- PTX helpers (baseline sm_80 ISA) ---------------------
__device__ __forceinline__ uint32_t smem_u32(const void* p) {
    uint32_t a;
    asm("{ .reg .u64 t; cvta.to.shared.u64 t, %1; cvt.u32.u64 %0, t; }"
        : "=r"(a) : "l"(p));
    return a;
}
__device__ __forceinline__ void cp16(uint32_t dst, const void* src) {
    asm volatile("cp.async.cg.shared.global [%0], [%1], 16;"
                 :: "r"(dst), "l"(src) : "memory");
}
__device__ __forceinline__ void cp_commit() {
    asm volatile("cp.async.commit_group;" ::: "memory");
}
__device__ __forceinline__ void ldx4(uint32_t* r, uint32_t addr) {
    asm volatile("ldmatrix.sync.aligned.m8n8.x4.shared.b16 {%0,%1,%2,%3}, [%4];"
                 : "=r"(r[0]), "=r"(r[1]), "=r"(r[2]), "=r"(r[3]) : "r"(addr));
}
__device__ __forceinline__ uint32_t tf32r(uint32_t x) {
    uint32_t r;
    asm("cvt.rna.tf32.f32 %0, %1;" : "=r"(r) : "f"(__uint_as_float(x)));
    return r;
}
__device__ __forceinline__ void mma_tf32(float* c, const uint32_t* a,
                                         const uint32_t* b) {
    asm volatile(
        "mma.sync.aligned.m16n8k8.row.col.f32.tf32.tf32.f32 "
        "{%0,%1,%2,%3}, {%4,%5,%6,%7}, {%8,%9}, {%0,%1,%2,%3};"
        : "+f"(c[0]), "+f"(c[1]), "+f"(c[2]), "+f"(c[3])
        : "r"(a[0]), "r"(a[1]), "r"(a[2]), "r"(a[3]), "r"(b[0]), "r"(b[1]));
}

// packed f32x2 helpers (per-lane IEEE fma, identical numerics to FFMA)
__device__ __forceinline__ unsigned long long pk2(float x, float y) {
    unsigned long long r;
    asm("mov.b64 %0, {%1, %2};" : "=l"(r) : "f"(x), "f"(y));
    return r;
}
__device__ __forceinline__ unsigned long long ff2(unsigned long long a,
                                                  unsigned long long b,
                                                  unsigned long long c) {
    unsigned long long d;
    asm("fma.rn.f32x2 %0, %1, %2, %3;" : "=l"(d) : "l"(a), "l"(b), "l"(c));
    return d;
}
__device__ __forceinline__ float f2lo(unsigned long long v) {
    return __uint_as_float((unsigned)(v & 0xffffffffull));
}
__device__ __forceinline__ float f2hi(unsigned long long v) {
    return __uint_as_float((unsigned)(v >> 32));
}

// -------------------- W transpose + tf32 round -----------------------------
__global__ __launch_bounds__(256) void convert_wT(const float* __restrict__ Wq,
                                                  const float* __restrict__ Wk,
                                                  const float* __restrict__ Wv) {
    const int z = blockIdx.z;
    const float* W = (z == 0 ? Wq : z == 1 ? Wk : Wv);
    __shared__ float t[32][33];
    const int tx = threadIdx.x & 31, ty = threadIdx.x >> 5;
    const int n0 = blockIdx.x * 32, k0 = blockIdx.y * 32;
#pragma unroll
    for (int j = 0; j < 32; j += 8)
        t[ty + j][tx] = W[(size_t)(k0 + ty + j) * GN + n0 + tx];
    __syncthreads();
#pragma unroll
    for (int j = 0; j < 32; j += 8) {
        uint32_t r = tf32r(__float_as_uint(t[tx][ty + j]));
        g_wt[z][(size_t)(n0 + ty + j) * GK + k0 + tx] = __uint_as_float(r);
    }
}

// tiny pad launches so ncu's captured launch index lands on gemm_tf32
__global__ void pad_kernel() {}

// -------------------- tf32 single-pass GEMM (unchanged from R14) -----------
constexpr int STG = 32768;            // A 16KB + B 16KB per stage
constexpr int NST = 3;
constexpr int GEMM_SMEM = NST * STG;  // 96KB
constexpr int NCHK = GK / 32;         // 32 k-chunks

__global__ __launch_bounds__(128, 2) void gemm_tf32(const float* __restrict__ q,
                                                    const float* __restrict__ k,
                                                    const float* __restrict__ v) {
    extern __shared__ char smem[];
    const uint32_t sb = smem_u32(smem);
    const int tid = threadIdx.x;
    const int wid = tid >> 5;
    const int lane = tid & 31;
    const int z = blockIdx.z;

    const float* A = (z == 0) ? q : (z == 1) ? k : v;
    const float* B = g_wt[z];
    float* C = (z == 0) ? g_Qp : (z == 1) ? g_Kp : g_Vp;
    const size_t rowBase = (size_t)blockIdx.y * 128;
    const size_t colBase = (size_t)blockIdx.x * 128;

    auto load_stage = [&](int chunk, int st) {
        const int k0 = chunk * 32;
        const uint32_t base = sb + st * STG;
#pragma unroll
        for (int j = 0; j < 8; j++) {
            int idx = tid + 128 * j;
            int r = idx >> 3, s = idx & 7;
            cp16(base + r * 128 + ((s ^ (r & 7)) * 16),
                 A + (rowBase + r) * GK + k0 + s * 4);
        }
#pragma unroll
        for (int j = 0; j < 8; j++) {
            int idx = tid + 128 * j;
            int r = idx >> 3, s = idx & 7;
            cp16(base + 16384 + r * 128 + ((s ^ (r & 7)) * 16),
                 B + (colBase + r) * GK + k0 + s * 4);
        }
        cp_commit();
    };

    load_stage(0, 0);
    load_stage(1, 1);

    const int wm = wid >> 1;        // 0..1  (M)
    const int wn = wid & 1;         // 0..1  (N)
    const int g = lane >> 3;        // ldmatrix group
    const int lr = lane & 7;
    const int aRow = (g & 1) * 8 + lr;   // A row within 16
    const int aC = g >> 1;               // A seg select
    const int bRow = (g >> 1) * 8 + lr;  // B n-row within 16
    const int bC = g & 1;                // B seg select

    float acc[4][8][4];
#pragma unroll
    for (int i = 0; i < 4; i++)
#pragma unroll
        for (int j = 0; j < 8; j++)
#pragma unroll
            for (int p = 0; p < 4; p++) acc[i][j][p] = 0.f;

#pragma unroll 1
    for (int c = 0; c < NCHK; c++) {
        if (c < NCHK - 1) {
            asm volatile("cp.async.wait_group 1;" ::: "memory");
        } else {
            asm volatile("cp.async.wait_group 0;" ::: "memory");
        }
        __syncthreads();
        if (c + 2 < NCHK) load_stage(c + 2, (c + 2) % 3);

        const uint32_t AB = sb + (c % 3) * STG;
        const uint32_t BB = AB + 16384;

#pragma unroll
        for (int ks = 0; ks < 4; ks++) {
            uint32_t af[4][4];
#pragma unroll
            for (int mt = 0; mt < 4; mt++) {
                int row = wm * 64 + mt * 16 + aRow;
                int seg = 2 * ks + aC;
                ldx4(af[mt], AB + row * 128 + ((seg ^ lr) * 16));
#pragma unroll
                for (int p = 0; p < 4; p++) af[mt][p] = tf32r(af[mt][p]);
            }
            uint32_t bf[4][4];
#pragma unroll
            for (int pr = 0; pr < 4; pr++) {
                int row = wn * 64 + pr * 16 + bRow;
                int seg = 2 * ks + bC;
                ldx4(bf[pr], BB + row * 128 + ((seg ^ lr) * 16));
            }
#pragma unroll
            for (int mt = 0; mt < 4; mt++)
#pragma unroll
                for (int nt = 0; nt < 8; nt++)
                    mma_tf32(acc[mt][nt], af[mt], &bf[nt >> 1][(nt & 1) * 2]);
        }
    }

    const int tg = lane >> 2, tt = lane & 3;
#pragma unroll
    for (int mt = 0; mt < 4; mt++) {
#pragma unroll
        for (int nt = 0; nt < 8; nt++) {
            size_t row0 = rowBase + wm * 64 + mt * 16 + tg;
            size_t col = colBase + wn * 64 + nt * 8 + 2 * tt;
            *(float2*)(C + row0 * GN + col) =
                make_float2(acc[mt][nt][0], acc[mt][nt][1]);
            *(float2*)(C + (row0 + 8) * GN + col) =
                make_float2(acc[mt][nt][2], acc[mt][nt][3]);
        }
    }
}

// ------------- LayerNorm(K), LayerNorm(V), partial P = Kn^T Vn -------------
// Hoisted row loads (MLP 8) + f32x2 outer product; numerics order-identical.
__global__ __launch_bounds__(256) void ln_pkv_kernel(const float* __restrict__ lnks,
                                                     const float* __restrict__ lnkb,
                                                     const float* __restrict__ lnvs,
                                                     const float* __restrict__ lnvb) {
    __shared__ float Ks[64][64];
    __shared__ float Vs[64][64];

    const int bh = blockIdx.y;
    const int chunk = blockIdx.x;
    const int h = bh & 15;

    const float* Kslab = g_Kp + (size_t)bh * (NSLAB * 64) + (size_t)chunk * 256 * 64;
    const float* Vslab = g_Vp + (size_t)bh * (NSLAB * 64) + (size_t)chunk * 256 * 64;

    const int tid = threadIdx.x;
    const int lane = tid & 31;
    const int warp = tid >> 5;
    const int tx = tid & 15;
    const int ty = tid >> 4;

    const float ks0 = lnks[h * 64 + 2 * lane], ks1 = lnks[h * 64 + 2 * lane + 1];
    const float kb0 = lnkb[h * 64 + 2 * lane], kb1 = lnkb[h * 64 + 2 * lane + 1];
    const float vs0 = lnvs[h * 64 + 2 * lane], vs1 = lnvs[h * 64 + 2 * lane + 1];
    const float vb0 = lnvb[h * 64 + 2 * lane], vb1 = lnvb[h * 64 + 2 * lane + 1];

    unsigned long long accp[4][2];
#pragma unroll
    for (int i = 0; i < 4; i++) {
        accp[i][0] = 0ull;
        accp[i][1] = 0ull;
    }

    for (int t = 0; t < 4; t++) {
        // ---- Phase A: LN 64 rows into smem; batched loads for MLP ----
        {
            float2 kv[8];
#pragma unroll
            for (int rr = 0; rr < 8; rr++) {
                int gr = t * 64 + warp * 8 + rr;
                kv[rr] = *(const float2*)(Kslab + (size_t)gr * 64 + 2 * lane);
            }
#pragma unroll
            for (int rr = 0; rr < 8; rr++) {
                int r = warp * 8 + rr;
                float s = kv[rr].x + kv[rr].y;
                float ss = kv[rr].x * kv[rr].x + kv[rr].y * kv[rr].y;
#pragma unroll
                for (int o = 16; o; o >>= 1) {
                    s  += __shfl_xor_sync(0xffffffffu, s, o);
                    ss += __shfl_xor_sync(0xffffffffu, ss, o);
                }
                float mean = s * (1.f / 64.f);
                float var = ss * (1.f / 64.f) - mean * mean;
                float rstd = rsqrtf(var + 1e-6f);
                Ks[r][2 * lane]     = (kv[rr].x - mean) * rstd * ks0 + kb0;
                Ks[r][2 * lane + 1] = (kv[rr].y - mean) * rstd * ks1 + kb1;
            }
        }
        {
            float2 vv[8];
#pragma unroll
            for (int rr = 0; rr < 8; rr++) {
                int gr = t * 64 + warp * 8 + rr;
                vv[rr] = *(const float2*)(Vslab + (size_t)gr * 64 + 2 * lane);
            }
#pragma unroll
            for (int rr = 0; rr < 8; rr++) {
                int r = warp * 8 + rr;
                float s = vv[rr].x + vv[rr].y;
                float ss = vv[rr].x * vv[rr].x + vv[rr].y * vv[rr].y;
#pragma unroll
                for (int o = 16; o; o >>= 1) {
                    s  += __shfl_xor_sync(0xffffffffu, s, o);
                    ss += __shfl_xor_sync(0xffffffffu, ss, o);
                }
                float mean = s * (1.f / 64.f);
                float var = ss * (1.f / 64.f) - mean * mean;
                float rstd = rsqrtf(var + 1e-6f);
                Vs[r][2 * lane]     = (vv[rr].x - mean) * rstd * vs0 + vb0;
                Vs[r][2 * lane + 1] = (vv[rr].y - mean) * rstd * vs1 + vb1;
            }
        }
        __syncthreads();
        // ---- Phase B: P[d][e] += sum_r Ks[r][d] * Vs[r][e]  (f32x2) ----
#pragma unroll 4
        for (int r = 0; r < 64; r++) {
            float4 a = *(const float4*)&Ks[r][ty * 4];
            ulonglong2 b = *(const ulonglong2*)&Vs[r][tx * 4];
            float av[4] = {a.x, a.y, a.z, a.w};
#pragma unroll
            for (int i = 0; i < 4; i++) {
                unsigned long long aa = pk2(av[i], av[i]);
                accp[i][0] = ff2(aa, b.x, accp[i][0]);
                accp[i][1] = ff2(aa, b.y, accp[i][1]);
            }
        }
        __syncthreads();
    }

    float* pp = g_Ppart + ((size_t)bh * NCHUNK + chunk) * 4096;
#pragma unroll
    for (int i = 0; i < 4; i++) {
        *(float4*)&pp[(ty * 4 + i) * 64 + tx * 4] =
            make_float4(f2lo(accp[i][0]), f2hi(accp[i][0]),
                        f2lo(accp[i][1]), f2hi(accp[i][1]));
    }
}

// ------------- deterministic reduction of P partials -> d_out p_attn -------
__global__ __launch_bounds__(256) void preduce_kernel(float* __restrict__ out) {
    const int bh = blockIdx.x;
    const float4* pp = (const float4*)(g_Ppart + (size_t)bh * NCHUNK * 4096);
    float4* po = (float4*)(out + ATT_SIZE + (size_t)bh * 4096);
    for (int idx = threadIdx.x; idx < 1024; idx += 256) {
        float4 s = make_float4(0.f, 0.f, 0.f, 0.f);
#pragma unroll
        for (int c = 0; c < NCHUNK; c++) {
            float4 p = pp[(size_t)c * 1024 + idx];
            s.x += p.x; s.y += p.y; s.z += p.z; s.w += p.w;
        }
        po[idx] = make_float4(s.x * (1.f / (float)NSLAB),
                              s.y * (1.f / (float)NSLAB),
                              s.z * (1.f / (float)NSLAB),
                              s.w * (1.f / (float)NSLAB));
    }
}

// ------------- x = Q_slab (8192x64) @ P (64x64), write att_output ----------
// f32x2 packed FMA halves the inner-loop FMA instruction count.
__global__ __launch_bounds__(256) void qp_kernel(float* __restrict__ out) {
    __shared__ float Ps[4096];
    __shared__ float Qs[64 * 68];

    const int bh = blockIdx.y;
    const int rc = blockIdx.x;

    const float* pin = out + ATT_SIZE + (size_t)bh * 4096;
    for (int i = threadIdx.x; i < 1024; i += 256)
        ((float4*)Ps)[i] = ((const float4*)pin)[i];

    const float* qsl = g_Qp + (size_t)bh * (NSLAB * 64) + (size_t)rc * 64 * 64;
    for (int i = threadIdx.x; i < 1024; i += 256) {
        float4 vv = ((const float4*)qsl)[i];
        int l = i * 4;
        int row = l >> 6;
        int col = l & 63;
        *(float4*)&Qs[row * 68 + col] = vv;
    }
    __syncthreads();

    const int row = threadIdx.x >> 2;
    const int c0 = (threadIdx.x & 3) * 16;

    unsigned long long accp[8];
#pragma unroll
    for (int j = 0; j < 8; j++) accp[j] = 0ull;

#pragma unroll 8
    for (int d = 0; d < 64; d++) {
        float qv = Qs[row * 68 + d];
        unsigned long long aa = pk2(qv, qv);
        ulonglong2 p0 = *(const ulonglong2*)&Ps[d * 64 + c0];
        ulonglong2 p1 = *(const ulonglong2*)&Ps[d * 64 + c0 + 4];
        ulonglong2 p2 = *(const ulonglong2*)&Ps[d * 64 + c0 + 8];
        ulonglong2 p3 = *(const ulonglong2*)&Ps[d * 64 + c0 + 12];
        accp[0] = ff2(aa, p0.x, accp[0]);
        accp[1] = ff2(aa, p0.y, accp[1]);
        accp[2] = ff2(aa, p1.x, accp[2]);
        accp[3] = ff2(aa, p1.y, accp[3]);
        accp[4] = ff2(aa, p2.x, accp[4]);
        accp[5] = ff2(aa, p2.y, accp[5]);
        accp[6] = ff2(aa, p3.x, accp[6]);
        accp[7] = ff2(aa, p3.y, accp[7]);
    }

    float* orow = out + (size_t)bh * (NSLAB * 64) + (size_t)rc * 64 * 64 + row * 64 + c0;
    *(float4*)(orow + 0)  = make_float4(f2lo(accp[0]), f2hi(accp[0]),
                                        f2lo(accp[1]), f2hi(accp[1]));
    *(float4*)(orow + 4)  = make_float4(f2lo(accp[2]), f2hi(accp[2]),
                                        f2lo(accp[3]), f2hi(accp[3]));
    *(float4*)(orow + 8)  = make_float4(f2lo(accp[4]), f2hi(accp[4]),
                                        f2lo(accp[5]), f2hi(accp[5]));
    *(float4*)(orow + 12) = make_float4(f2lo(accp[6]), f2hi(accp[6]),
                                        f2lo(accp[7]), f2hi(accp[7]));
}

extern "C" void kernel_launch(void* const* d_in, const int* in_sizes, int n_in,
                              void* d_out, int out_size) {
    const float* query = (const float*)d_in[0];
    const float* key   = (const float*)d_in[1];
    const float* value = (const float*)d_in[2];
    const float* Wq    = (const float*)d_in[3];
    const float* Wk    = (const float*)d_in[4];
    const float* Wv    = (const float*)d_in[5];
    const float* lnks  = (const float*)d_in[6];
    const float* lnkb  = (const float*)d_in[7];
    const float* lnvs  = (const float*)d_in[8];
    const float* lnvb  = (const float*)d_in[9];
    float* out = (float*)d_out;

    cudaFuncSetAttribute(gemm_tf32, cudaFuncAttributeMaxDynamicSharedMemorySize,
                         GEMM_SMEM);

    convert_wT<<<dim3(32, 32, 3), 256>>>(Wq, Wk, Wv);   // launch 1
    pad_kernel<<<1, 32>>>();                            // launch 2
    pad_kernel<<<1, 32>>>();                            // launch 3
    gemm_tf32<<<dim3(GN / 128, GM / 128, 3), 128, GEMM_SMEM>>>(query, key, value); // 4
    ln_pkv_kernel<<<dim3(NCHUNK, NBH), 256>>>(lnks, lnkb, lnvs, lnvb);
    preduce_kernel<<<NBH, 256>>>(out);
    qp_kernel<<<dim3(NSLAB / 64, NBH), 256>>>(out);
}